// round 12
// baseline (speedup 1.0000x reference)
#include <cuda_runtime.h>
#include <cuda_bf16.h>

// ---------------------------------------------------------------------------
// GraphLogitLayers: conv3x3(circular)+relu+mean-pool -> edge MLP -> node MLP.
// P=4, B=128, C=32, H=W=64, HID=64. NIMG = 512.
// Conv: INT8 implicit-GEMM via mma.sync.m16n8k32.s8 (2x MAC density vs bf16;
//       sm_80 instruction => compiles on compute_103). K=32 covers all of CIN
//       in one mma. Per-oc dynamic weight scales, x clipped at +-5 sigma,
//       exact s32 accumulation, f32 epilogue (scale+bias+relu+pool).
// MLP:  R11 version verbatim (fused node reduction, rank-1 edge decomp).
// ---------------------------------------------------------------------------

#define NIMG   512
#define CIN    32
#define WW     64
#define COUT   64
#define HID    64
#define NSLOT  64          // 16 row-tiles * 4 sp-warps
#define XCLIP  5.0f
#define XSCALE (127.0f / XCLIP)

// device scratch (no allocations allowed)
__device__ alignas(16) float g_partial[NSLOT * NIMG * COUT];   // 8 MB
__device__ alignas(16) uint4 g_wa[9 * 4 * 32];                 // [tap][mtg][lane]
__device__ alignas(16) float g_scl[2 * COUT];  // [oc]: 127/max ; [64+oc]: epi mult

// ---------------------------------------------------------------------------
// prep_scale: per-oc max|w| -> pack scale (127/max) and epilogue multiplier
// (max * XCLIP / (127*127)).  One block, 256 threads (4 per oc).
// ---------------------------------------------------------------------------
__global__ void prep_scale_kernel(const float* __restrict__ w) {
    __shared__ float smax[256];
    const int t  = threadIdx.x;
    const int oc = t >> 2;
    const int q  = t & 3;
    float m = 0.f;
    const float* wp = w + oc * 288 + q * 72;
    for (int i = 0; i < 72; i++) m = fmaxf(m, fabsf(wp[i]));
    smax[t] = m;
    __syncthreads();
    if (q == 0) {
        float mm = fmaxf(fmaxf(smax[t], smax[t + 1]), fmaxf(smax[t + 2], smax[t + 3]));
        g_scl[oc]        = 127.f / mm;
        g_scl[64 + oc]   = mm * XCLIP / (127.f * 127.f);
    }
}

// ---------------------------------------------------------------------------
// prep_pack: pack weights into m16n8k32 s8 A-fragment order.
// g_wa[(tap*4 + mtg)*32 + lane] = {a0,a1,a2,a3}:
//   a0: oc = mtg*16 + (lane>>2),      ic = (lane&3)*4 + 0..3
//   a1: oc + 8, same ic;   a2: oc, ic+16;   a3: oc+8, ic+16
// ---------------------------------------------------------------------------
__global__ void prep_pack_kernel(const float* __restrict__ w) {
    int i = blockIdx.x * blockDim.x + threadIdx.x;
    if (i >= 1152) return;
    int lane = i & 31;
    int mtg  = (i >> 5) & 3;
    int tap  = i >> 7;               // 0..8
    int kh = tap / 3, kw = tap % 3;
    unsigned r[4];
#pragma unroll
    for (int rr = 0; rr < 4; rr++) {
        int oc  = mtg * 16 + (lane >> 2) + ((rr & 1) << 3);
        int icb = ((lane & 3) << 2) + ((rr >> 1) << 4);
        float s = g_scl[oc];
        unsigned pk = 0;
#pragma unroll
        for (int j = 0; j < 4; j++) {
            float v = w[(oc * CIN + icb + j) * 9 + kh * 3 + kw] * s;
            int qv = __float2int_rn(fminf(fmaxf(v, -127.f), 127.f));
            pk |= (unsigned)((unsigned char)(char)qv) << (8 * j);
        }
        r[rr] = pk;
    }
    g_wa[i] = make_uint4(r[0], r[1], r[2], r[3]);
}

// ---------------------------------------------------------------------------
__device__ __forceinline__ void mma_s8(int* c, const unsigned* a,
                                       unsigned b0, unsigned b1) {
    asm volatile(
        "mma.sync.aligned.m16n8k32.row.col.s32.s8.s8.s32 "
        "{%0,%1,%2,%3}, {%4,%5,%6,%7}, {%8,%9}, {%0,%1,%2,%3};\n"
        : "+r"(c[0]), "+r"(c[1]), "+r"(c[2]), "+r"(c[3])
        : "r"(a[0]), "r"(a[1]), "r"(a[2]), "r"(a[3]), "r"(b0), "r"(b1));
}

// ---------------------------------------------------------------------------
// Fused int8 conv + scale + bias + relu + spatial partial-sum.
// Grid (16 row-tiles, 512 imgs), 256 threads (8 warps = 4 sp x 2 oc).
// Block tile: 4 rows x 64 cols x 64 oc. Warp: 32 oc x 64 sp (one row).
// Smem: s8 [6 rows][66 cols(halo)][ic stride 48] = 19008 B.
//   Stride 48 => the 8 lane-groups of a B-fragment LDS.32 hit 8 distinct
//   bank quads (12n mod 32 pattern) -> conflict-free.
// Per tap: ONE k=32 mma per (nt, mt): 9*8*2 = 144 QMMA, 144 LDS.32/lane.
// ---------------------------------------------------------------------------
#define SPS 48    // ic stride (bytes) per spatial position

__global__ __launch_bounds__(256, 2)
void conv_pool_kernel(const float* __restrict__ x, const float* __restrict__ conv_b) {
    __shared__ alignas(16) char tile[6 * 66 * SPS];   // 19008 B

    const int n   = blockIdx.y;
    const int rt  = blockIdx.x;
    const int h0  = rt * 4;
    const int tid = threadIdx.x;
    const float* xb = x + ((long)n << 17);

    // interior columns: float4 over w (16 float4 per (rr,ic) row), quantize s8
    for (int idx = tid; idx < 6 * CIN * 16; idx += 256) {
        int w4   = idx & 15;
        int rest = idx >> 4;
        int ic   = rest & 31;
        int rr   = rest >> 5;                        // 0..5
        int gh   = (h0 + rr + 63) & 63;
        float4 f = ((const float4*)(xb + (ic << 12) + (gh << 6)))[w4];
        char* dst = &tile[(rr * 66 + w4 * 4 + 1) * SPS + ic];
        dst[0]       = (char)__float2int_rn(fminf(fmaxf(f.x * XSCALE, -127.f), 127.f));
        dst[SPS]     = (char)__float2int_rn(fminf(fmaxf(f.y * XSCALE, -127.f), 127.f));
        dst[2 * SPS] = (char)__float2int_rn(fminf(fmaxf(f.z * XSCALE, -127.f), 127.f));
        dst[3 * SPS] = (char)__float2int_rn(fminf(fmaxf(f.w * XSCALE, -127.f), 127.f));
    }
    // circular halo columns
    for (int idx = tid; idx < 6 * CIN * 2; idx += 256) {
        int side = idx & 1;
        int rest = idx >> 1;
        int ic   = rest & 31;
        int rr   = rest >> 5;
        int gh   = (h0 + rr + 63) & 63;
        int gw   = side ? 0 : 63;
        int c    = side ? 65 : 0;
        float v  = xb[(ic << 12) + (gh << 6) + gw];
        tile[(rr * 66 + c) * SPS + ic] =
            (char)__float2int_rn(fminf(fmaxf(v * XSCALE, -127.f), 127.f));
    }
    __syncthreads();

    const int lane   = tid & 31;
    const int warp   = tid >> 5;
    const int warpOc = warp & 1;     // 2 oc groups of 32
    const int warpSp = warp >> 1;    // 4 sp groups = block-tile rows

    // per-lane B offset: sp-part (lane>>2)*SPS, k-part (lane&3)*4 bytes
    const char* bbase = tile + (lane >> 2) * SPS + ((lane & 3) << 2);

    int acc[8][2][4];
#pragma unroll
    for (int nt = 0; nt < 8; nt++)
#pragma unroll
        for (int mt = 0; mt < 2; mt++)
#pragma unroll
            for (int c = 0; c < 4; c++) acc[nt][mt][c] = 0;

    for (int kh = 0; kh < 3; kh++) {
        for (int kw = 0; kw < 3; kw++) {
            const int tap = kh * 3 + kw;
            uint4 a0 = g_wa[(tap * 4 + warpOc * 2 + 0) * 32 + lane];
            uint4 a1 = g_wa[(tap * 4 + warpOc * 2 + 1) * 32 + lane];
            const char* tb = bbase + ((warpSp + kh) * 66 + kw) * SPS;
#pragma unroll
            for (int nt = 0; nt < 8; nt++) {
                unsigned b0 = *(const unsigned*)(tb + nt * (8 * SPS));
                unsigned b1 = *(const unsigned*)(tb + nt * (8 * SPS) + 16);
                mma_s8(acc[nt][0], (const unsigned*)&a0, b0, b1);
                mma_s8(acc[nt][1], (const unsigned*)&a1, b0, b1);
            }
        }
    }

    // epilogue: dequant scale + bias + relu + sum over spatial, reduce lane&3
    const int rowa = lane >> 2;
#pragma unroll
    for (int mt = 0; mt < 2; mt++) {
        int oc = warpOc * 32 + mt * 16 + rowa;
        float sc0 = g_scl[64 + oc];
        float sc1 = g_scl[64 + oc + 8];
        float bs0 = conv_b[oc];
        float bs1 = conv_b[oc + 8];
        float s0 = 0.f, s1 = 0.f;
#pragma unroll
        for (int nt = 0; nt < 8; nt++) {
            s0 += fmaxf((float)acc[nt][mt][0] * sc0 + bs0, 0.f)
                + fmaxf((float)acc[nt][mt][1] * sc0 + bs0, 0.f);
            s1 += fmaxf((float)acc[nt][mt][2] * sc1 + bs1, 0.f)
                + fmaxf((float)acc[nt][mt][3] * sc1 + bs1, 0.f);
        }
        s0 += __shfl_xor_sync(0xffffffffu, s0, 1);
        s0 += __shfl_xor_sync(0xffffffffu, s0, 2);
        s1 += __shfl_xor_sync(0xffffffffu, s1, 1);
        s1 += __shfl_xor_sync(0xffffffffu, s1, 2);
        if ((lane & 3) == 0) {
            int slot = rt * 4 + warpSp;
            g_partial[slot * (NIMG * COUT) + (n << 6) + oc]     = s0;
            g_partial[slot * (NIMG * COUT) + (n << 6) + oc + 8] = s1;
        }
    }
}

// ---------------------------------------------------------------------------
// Graph MLP with fused node reduction (R11 verbatim). 32 blocks x 1024
// threads; 4 batches/block, smem weight staging, rank-1 edge decomposition.
// ---------------------------------------------------------------------------
#define MLP_SLAB 2064
#define MLP_DYN  ((16704 + 4 * MLP_SLAB) * 4)    // 99840 B

__global__ __launch_bounds__(1024)
void mlp_kernel(const float* __restrict__ e_w1, const float* __restrict__ e_b1,
                const float* __restrict__ e_w2, const float* __restrict__ e_b2,
                const float* __restrict__ o_w1, const float* __restrict__ o_b1,
                const float* __restrict__ o_w2, const float* __restrict__ o_b2,
                float* __restrict__ out) {
    extern __shared__ float ws[];
    float* W1  = ws;
    float* W2  = ws + 8192;
    float* OW1 = ws + 12288;
    float* OW2 = ws + 16384;
    float* B1  = ws + 16448;
    float* B2  = ws + 16512;
    float* OB1 = ws + 16576;

    const int tid  = threadIdx.x;
    const int bg   = tid >> 8;          // batch group 0..3
    const int t256 = tid & 255;
    const int g    = t256 >> 6;         // node 0..3
    const int h    = t256 & 63;
    const int b    = blockIdx.x * 4 + bg;

    float* slab = ws + 16704 + bg * MLP_SLAB;
    float* sN  = slab;
    float* sA  = slab + 256;
    float* sC  = slab + 512;
    float* sE  = slab + 768;    // [i][j][h] = [(i*4+j)*64+h]
    float* sM  = slab + 1792;
    float* red = slab + 2048;

    // fused node reduction: nodes[b][g][h] from 64 partial slots
    {
        const float* p = g_partial + (g * 128 + b) * 64 + h;
        float s = 0.f;
#pragma unroll
        for (int k = 0; k < NSLOT; k++) s += p[k * (NIMG * COUT)];
        sN[g * 64 + h] = s * (1.f / 4096.f);
    }

    for (int i = tid; i < 8192; i += 1024) W1[i]  = e_w1[i];
    for (int i = tid; i < 4096; i += 1024) W2[i]  = e_w2[i];
    for (int i = tid; i < 4096; i += 1024) OW1[i] = o_w1[i];
    if (tid < 64) {
        OW2[tid] = o_w2[tid];
        B1[tid]  = e_b1[tid];
        B2[tid]  = e_b2[tid];
        OB1[tid] = o_b1[tid];
    }
    if (tid == 0) ws[16640] = o_b2[0];
    __syncthreads();

    // a_g = n_g @ W_top + b1 ; c_g = n_g @ W_bot
    {
        float a0 = B1[h], a1 = 0.f, c0 = 0.f, c1 = 0.f;
#pragma unroll 8
        for (int k = 0; k < 64; k += 2) {
            float n0 = sN[g * 64 + k], n1 = sN[g * 64 + k + 1];
            a0 = fmaf(n0, W1[k * 64 + h], a0);
            a1 = fmaf(n1, W1[(k + 1) * 64 + h], a1);
            c0 = fmaf(n0, W1[(64 + k) * 64 + h], c0);
            c1 = fmaf(n1, W1[(64 + k + 1) * 64 + h], c1);
        }
        sA[g * 64 + h] = a0 + a1;
        sC[g * 64 + h] = c0 + c1;
    }
    __syncthreads();
    // e1[i=g][j][h] = relu(a_i + c_j)
    {
        float a = sA[g * 64 + h];
#pragma unroll
        for (int j = 0; j < 4; j++)
            sE[(g * 4 + j) * 64 + h] = fmaxf(a + sC[j * 64 + h], 0.f);
    }
    __syncthreads();
    // msg[j=g][h] = mean_i relu(e1[i][g] @ W2 + b2)
    {
        float m = 0.f;
        for (int i = 0; i < 4; i++) {
            float q0 = B2[h], q1 = 0.f;
            const float* e = sE + (i * 4 + g) * 64;
#pragma unroll 8
            for (int k = 0; k < 64; k += 2) {
                q0 = fmaf(e[k],     W2[k * 64 + h],       q0);
                q1 = fmaf(e[k + 1], W2[(k + 1) * 64 + h], q1);
            }
            m += fmaxf(q0 + q1, 0.f);
        }
        sM[g * 64 + h] = m * 0.25f;
    }
    __syncthreads();
    // o1 + final dot with o_w2
    {
        float q0 = OB1[h], q1 = 0.f;
#pragma unroll 8
        for (int k = 0; k < 64; k += 2) {
            q0 = fmaf(sM[g * 64 + k],     OW1[k * 64 + h],       q0);
            q1 = fmaf(sM[g * 64 + k + 1], OW1[(k + 1) * 64 + h], q1);
        }
        float v = fmaxf(q0 + q1, 0.f) * OW2[h];
#pragma unroll
        for (int m = 16; m >= 1; m >>= 1) v += __shfl_xor_sync(0xffffffffu, v, m);
        if ((t256 & 31) == 0) red[t256 >> 5] = v;
    }
    __syncthreads();
    if (t256 < 4) out[b * 4 + t256] = red[2 * t256] + red[2 * t256 + 1] + ws[16640];
}

// ---------------------------------------------------------------------------
extern "C" void kernel_launch(void* const* d_in, const int* in_sizes, int n_in,
                              void* d_out, int out_size) {
    const float* x      = (const float*)d_in[0];
    const float* conv_w = (const float*)d_in[1];
    const float* conv_b = (const float*)d_in[2];
    const float* e_w1   = (const float*)d_in[3];
    const float* e_b1   = (const float*)d_in[4];
    const float* e_w2   = (const float*)d_in[5];
    const float* e_b2   = (const float*)d_in[6];
    const float* o_w1   = (const float*)d_in[7];
    const float* o_b1   = (const float*)d_in[8];
    const float* o_w2   = (const float*)d_in[9];
    const float* o_b2   = (const float*)d_in[10];
    float* out = (float*)d_out;

    // idempotent, called every launch (no static guards per harness rules)
    cudaFuncSetAttribute(mlp_kernel,
                         cudaFuncAttributeMaxDynamicSharedMemorySize, MLP_DYN);

    prep_scale_kernel<<<1, 256>>>(conv_w);
    prep_pack_kernel<<<5, 256>>>(conv_w);

    dim3 grid(16, NIMG);
    conv_pool_kernel<<<grid, 256>>>(x, conv_b);

    mlp_kernel<<<32, 1024, MLP_DYN>>>(e_w1, e_b1, e_w2, e_b2,
                                      o_w1, o_b1, o_w2, o_b2, out);
}

// round 13
// speedup vs baseline: 1.6160x; 1.6160x over previous
#include <cuda_runtime.h>
#include <cuda_bf16.h>

// ---------------------------------------------------------------------------
// GraphLogitLayers: conv3x3(circular)+relu+mean-pool -> edge MLP -> node MLP.
// P=4, B=128, C=32, H=W=64, HID=64. NIMG = 512.
// FINAL (R11 proven, 340.5us): bf16 mma.sync implicit-GEMM conv at ~89% of
// its HMMA pipe floor + fused-reduction smem-staged MLP.
// Falsified alternatives: tcgen05 (harness PTX target compute_103 lacks 'a'
// features), Winograd F(2,3) (net regression), int8 m16n8k32 (IMMA de-rated
// vs HMMA on sm_103 legacy path, R12: 1.4x slower).
// ---------------------------------------------------------------------------

#define NIMG   512
#define CIN    32
#define WW     64
#define COUT   64
#define HID    64
#define NSLOT  64          // 16 row-tiles * 4 sp-warps

// device scratch (no allocations allowed)
__device__ alignas(16) float g_partial[NSLOT * NIMG * COUT];   // 8 MB
__device__ alignas(16) uint4 g_wa[9 * 2 * 4 * 32];             // [tap][ks][mt][lane]

// ---------------------------------------------------------------------------
// prep: pack conv weights into mma A-fragment order (bf16x2 per reg, uint4 per
// lane): reg r of lane l for (tap, ks, mt):
//   m = mt*16 + (r&1)*8 + (l>>2),  k = ks*16 + (r>>1)*8 + 2*(l&3) (+1 hi half)
// ---------------------------------------------------------------------------
__global__ void prep_kernel(const float* __restrict__ w) {
    int i = blockIdx.x * blockDim.x + threadIdx.x;
    if (i >= 2304) return;
    int lane = i & 31;
    int mt   = (i >> 5) & 3;
    int ks   = (i >> 7) & 1;
    int tap  = i >> 8;
    int kh = tap / 3, kw = tap % 3;
    unsigned r[4];
#pragma unroll
    for (int rr = 0; rr < 4; rr++) {
        int m = mt * 16 + ((rr & 1) << 3) + (lane >> 2);
        int k = ks * 16 + ((rr >> 1) << 3) + ((lane & 3) << 1);
        unsigned lo = __bfloat16_as_ushort(__float2bfloat16(w[((m * CIN + k    ) * 3 + kh) * 3 + kw]));
        unsigned hi = __bfloat16_as_ushort(__float2bfloat16(w[((m * CIN + k + 1) * 3 + kh) * 3 + kw]));
        r[rr] = lo | (hi << 16);
    }
    g_wa[i] = make_uint4(r[0], r[1], r[2], r[3]);
}

// ---------------------------------------------------------------------------
__device__ __forceinline__ void mma_bf16(float* c, const unsigned* a,
                                         unsigned b0, unsigned b1) {
    asm volatile(
        "mma.sync.aligned.m16n8k16.row.col.f32.bf16.bf16.f32 "
        "{%0,%1,%2,%3}, {%4,%5,%6,%7}, {%8,%9}, {%0,%1,%2,%3};\n"
        : "+f"(c[0]), "+f"(c[1]), "+f"(c[2]), "+f"(c[3])
        : "r"(a[0]), "r"(a[1]), "r"(a[2]), "r"(a[3]), "r"(b0), "r"(b1));
}

__device__ __forceinline__ void ldsm_x4(unsigned& r0, unsigned& r1,
                                        unsigned& r2, unsigned& r3, unsigned addr) {
    asm volatile("ldmatrix.sync.aligned.m8n8.x4.shared.b16 {%0,%1,%2,%3}, [%4];\n"
                 : "=r"(r0), "=r"(r1), "=r"(r2), "=r"(r3) : "r"(addr));
}

// ---------------------------------------------------------------------------
// Fused conv + bias + relu + spatial partial-sum.
// Grid (16 row-tiles, 512 imgs), 256 threads (8 warps).
// Block tile: 4 rows x 64 cols x 64 oc. Warp: 32 oc x 64 sp (one row).
// Smem: 6 rows x 66 cols (circular halo) x ic, ic padded to ICP=40.
// Staging uses float4 global loads (12 LDG.128/thread vs 50 LDG.32).
// ---------------------------------------------------------------------------
#define ICP 40

__global__ __launch_bounds__(256, 2)
void conv_pool_kernel(const float* __restrict__ x, const float* __restrict__ conv_b) {
    __shared__ alignas(16) __nv_bfloat16 tile[6 * 66 * ICP];   // 31680 B

    const int n   = blockIdx.y;
    const int rt  = blockIdx.x;
    const int h0  = rt * 4;
    const int tid = threadIdx.x;
    const float* xb = x + ((long)n << 17);

    // interior columns: float4 over w (16 float4 per (rr,ic) row)
    for (int idx = tid; idx < 6 * CIN * 16; idx += 256) {
        int w4   = idx & 15;
        int rest = idx >> 4;
        int ic   = rest & 31;
        int rr   = rest >> 5;                        // 0..5
        int gh   = (h0 + rr + 63) & 63;
        float4 f = ((const float4*)(xb + (ic << 12) + (gh << 6)))[w4];
        __nv_bfloat16* dst = &tile[(rr * 66 + w4 * 4 + 1) * ICP + ic];
        dst[0]       = __float2bfloat16(f.x);
        dst[ICP]     = __float2bfloat16(f.y);
        dst[2 * ICP] = __float2bfloat16(f.z);
        dst[3 * ICP] = __float2bfloat16(f.w);
    }
    // circular halo columns
    for (int idx = tid; idx < 6 * CIN * 2; idx += 256) {
        int side = idx & 1;
        int rest = idx >> 1;
        int ic   = rest & 31;
        int rr   = rest >> 5;
        int gh   = (h0 + rr + 63) & 63;
        int gw   = side ? 0 : 63;
        int c    = side ? 65 : 0;
        tile[(rr * 66 + c) * ICP + ic] =
            __float2bfloat16(xb[(ic << 12) + (gh << 6) + gw]);
    }
    __syncthreads();

    const int lane   = tid & 31;
    const int warp   = tid >> 5;
    const int warpOc = warp & 1;     // 2 oc groups of 32
    const int warpSp = warp >> 1;    // 4 sp groups = block-tile rows

    unsigned sbase = (unsigned)__cvta_generic_to_shared(tile) +
                     (((warpSp * 66 + (lane & 7)) * ICP + ((lane >> 3) << 3)) << 1);

    float acc[8][2][4];
#pragma unroll
    for (int nt = 0; nt < 8; nt++)
#pragma unroll
        for (int mt = 0; mt < 2; mt++)
#pragma unroll
            for (int c = 0; c < 4; c++) acc[nt][mt][c] = 0.f;

    for (int kh = 0; kh < 3; kh++) {
        for (int kw = 0; kw < 3; kw++) {
            const int tap = kh * 3 + kw;
            uint4 a00 = g_wa[((tap * 2 + 0) * 4 + warpOc * 2 + 0) * 32 + lane];
            uint4 a01 = g_wa[((tap * 2 + 0) * 4 + warpOc * 2 + 1) * 32 + lane];
            uint4 a10 = g_wa[((tap * 2 + 1) * 4 + warpOc * 2 + 0) * 32 + lane];
            uint4 a11 = g_wa[((tap * 2 + 1) * 4 + warpOc * 2 + 1) * 32 + lane];
            unsigned tapaddr = sbase + (unsigned)(((kh * 66 + kw) * ICP) << 1);
#pragma unroll
            for (int nt = 0; nt < 8; nt++) {
                unsigned b0, b1, b2, b3;
                ldsm_x4(b0, b1, b2, b3, tapaddr + nt * (8 * ICP * 2));
                mma_bf16(acc[nt][0], (const unsigned*)&a00, b0, b1);
                mma_bf16(acc[nt][1], (const unsigned*)&a01, b0, b1);
                mma_bf16(acc[nt][0], (const unsigned*)&a10, b2, b3);
                mma_bf16(acc[nt][1], (const unsigned*)&a11, b2, b3);
            }
        }
    }

    // epilogue: bias + relu + sum over spatial, reduce over (lane&3)
    const int rowa = lane >> 2;
#pragma unroll
    for (int mt = 0; mt < 2; mt++) {
        int oc = warpOc * 32 + mt * 16 + rowa;
        float bs0 = conv_b[oc];
        float bs1 = conv_b[oc + 8];
        float s0 = 0.f, s1 = 0.f;
#pragma unroll
        for (int nt = 0; nt < 8; nt++) {
            s0 += fmaxf(acc[nt][mt][0] + bs0, 0.f) + fmaxf(acc[nt][mt][1] + bs0, 0.f);
            s1 += fmaxf(acc[nt][mt][2] + bs1, 0.f) + fmaxf(acc[nt][mt][3] + bs1, 0.f);
        }
        s0 += __shfl_xor_sync(0xffffffffu, s0, 1);
        s0 += __shfl_xor_sync(0xffffffffu, s0, 2);
        s1 += __shfl_xor_sync(0xffffffffu, s1, 1);
        s1 += __shfl_xor_sync(0xffffffffu, s1, 2);
        if ((lane & 3) == 0) {
            int slot = rt * 4 + warpSp;
            g_partial[slot * (NIMG * COUT) + (n << 6) + oc]     = s0;
            g_partial[slot * (NIMG * COUT) + (n << 6) + oc + 8] = s1;
        }
    }
}

// ---------------------------------------------------------------------------
// Graph MLP with fused node reduction. 32 blocks x 1024 threads; 4 batches
// per block share one weight staging. Each 256-thread batch-group: 4 node
// groups g x 64 hid h. Head: each thread reduces the 64 partial slots for
// its own node element (same k-order as a standalone reduce -> bit-equal).
// Rank-1 decomposition: e1(i,j) = relu(a_i + c_j).
// ---------------------------------------------------------------------------
#define MLP_SLAB 2064
#define MLP_DYN  ((16704 + 4 * MLP_SLAB) * 4)    // 99840 B

__global__ __launch_bounds__(1024)
void mlp_kernel(const float* __restrict__ e_w1, const float* __restrict__ e_b1,
                const float* __restrict__ e_w2, const float* __restrict__ e_b2,
                const float* __restrict__ o_w1, const float* __restrict__ o_b1,
                const float* __restrict__ o_w2, const float* __restrict__ o_b2,
                float* __restrict__ out) {
    extern __shared__ float ws[];
    float* W1  = ws;
    float* W2  = ws + 8192;
    float* OW1 = ws + 12288;
    float* OW2 = ws + 16384;
    float* B1  = ws + 16448;
    float* B2  = ws + 16512;
    float* OB1 = ws + 16576;

    const int tid  = threadIdx.x;
    const int bg   = tid >> 8;          // batch group 0..3
    const int t256 = tid & 255;
    const int g    = t256 >> 6;         // node 0..3
    const int h    = t256 & 63;
    const int b    = blockIdx.x * 4 + bg;

    float* slab = ws + 16704 + bg * MLP_SLAB;
    float* sN  = slab;
    float* sA  = slab + 256;
    float* sC  = slab + 512;
    float* sE  = slab + 768;    // [i][j][h] = [(i*4+j)*64+h]
    float* sM  = slab + 1792;
    float* red = slab + 2048;

    // ---- fused node reduction: nodes[b][g][h] from 64 partial slots ----
    {
        const float* p = g_partial + (g * 128 + b) * 64 + h;
        float s = 0.f;
#pragma unroll
        for (int k = 0; k < NSLOT; k++) s += p[k * (NIMG * COUT)];
        sN[g * 64 + h] = s * (1.f / 4096.f);
    }

    // ---- weight staging: all 1024 threads ----
    for (int i = tid; i < 8192; i += 1024) W1[i]  = e_w1[i];
    for (int i = tid; i < 4096; i += 1024) W2[i]  = e_w2[i];
    for (int i = tid; i < 4096; i += 1024) OW1[i] = o_w1[i];
    if (tid < 64) {
        OW2[tid] = o_w2[tid];
        B1[tid]  = e_b1[tid];
        B2[tid]  = e_b2[tid];
        OB1[tid] = o_b1[tid];
    }
    if (tid == 0) ws[16640] = o_b2[0];
    __syncthreads();

    // a_g = n_g @ W_top + b1 ; c_g = n_g @ W_bot
    {
        float a0 = B1[h], a1 = 0.f, c0 = 0.f, c1 = 0.f;
#pragma unroll 8
        for (int k = 0; k < 64; k += 2) {
            float n0 = sN[g * 64 + k], n1 = sN[g * 64 + k + 1];
            a0 = fmaf(n0, W1[k * 64 + h], a0);
            a1 = fmaf(n1, W1[(k + 1) * 64 + h], a1);
            c0 = fmaf(n0, W1[(64 + k) * 64 + h], c0);
            c1 = fmaf(n1, W1[(64 + k + 1) * 64 + h], c1);
        }
        sA[g * 64 + h] = a0 + a1;
        sC[g * 64 + h] = c0 + c1;
    }
    __syncthreads();
    // e1[i=g][j][h] = relu(a_i + c_j)
    {
        float a = sA[g * 64 + h];
#pragma unroll
        for (int j = 0; j < 4; j++)
            sE[(g * 4 + j) * 64 + h] = fmaxf(a + sC[j * 64 + h], 0.f);
    }
    __syncthreads();
    // msg[j=g][h] = mean_i relu(e1[i][g] @ W2 + b2)
    {
        float m = 0.f;
        for (int i = 0; i < 4; i++) {
            float q0 = B2[h], q1 = 0.f;
            const float* e = sE + (i * 4 + g) * 64;
#pragma unroll 8
            for (int k = 0; k < 64; k += 2) {
                q0 = fmaf(e[k],     W2[k * 64 + h],       q0);
                q1 = fmaf(e[k + 1], W2[(k + 1) * 64 + h], q1);
            }
            m += fmaxf(q0 + q1, 0.f);
        }
        sM[g * 64 + h] = m * 0.25f;
    }
    __syncthreads();
    // o1 + final dot with o_w2
    {
        float q0 = OB1[h], q1 = 0.f;
#pragma unroll 8
        for (int k = 0; k < 64; k += 2) {
            q0 = fmaf(sM[g * 64 + k],     OW1[k * 64 + h],       q0);
            q1 = fmaf(sM[g * 64 + k + 1], OW1[(k + 1) * 64 + h], q1);
        }
        float v = fmaxf(q0 + q1, 0.f) * OW2[h];
#pragma unroll
        for (int m = 16; m >= 1; m >>= 1) v += __shfl_xor_sync(0xffffffffu, v, m);
        if ((t256 & 31) == 0) red[t256 >> 5] = v;
    }
    __syncthreads();
    if (t256 < 4) out[b * 4 + t256] = red[2 * t256] + red[2 * t256 + 1] + ws[16640];
}

// ---------------------------------------------------------------------------
extern "C" void kernel_launch(void* const* d_in, const int* in_sizes, int n_in,
                              void* d_out, int out_size) {
    const float* x      = (const float*)d_in[0];
    const float* conv_w = (const float*)d_in[1];
    const float* conv_b = (const float*)d_in[2];
    const float* e_w1   = (const float*)d_in[3];
    const float* e_b1   = (const float*)d_in[4];
    const float* e_w2   = (const float*)d_in[5];
    const float* e_b2   = (const float*)d_in[6];
    const float* o_w1   = (const float*)d_in[7];
    const float* o_b1   = (const float*)d_in[8];
    const float* o_w2   = (const float*)d_in[9];
    const float* o_b2   = (const float*)d_in[10];
    float* out = (float*)d_out;

    // idempotent, called every launch (no static guards per harness rules)
    cudaFuncSetAttribute(mlp_kernel,
                         cudaFuncAttributeMaxDynamicSharedMemorySize, MLP_DYN);

    prep_kernel<<<9, 256>>>(conv_w);

    dim3 grid(16, NIMG);
    conv_pool_kernel<<<grid, 256>>>(x, conv_b);

    mlp_kernel<<<32, 1024, MLP_DYN>>>(e_w1, e_b1, e_w2, e_b2,
                                      o_w1, o_b1, o_w2, o_b2, out);
}